// round 2
// baseline (speedup 1.0000x reference)
#include <cuda_runtime.h>
#include <cuda_bf16.h>

#define N_NODES  100000
#define N_EDGES  600000
#define N_GRAPHS 512
#define EMBD     128
#define HIDD     128

// ---------------- scratch (device globals; no allocations allowed) ----------
__device__ float g_deg[N_NODES];
__device__ float g_dis[N_NODES];
__device__ float g_a0[(size_t)N_NODES * EMBD];   // agg of embeddings (layer-1 input)
__device__ float g_h1[(size_t)N_NODES * HIDD];   // relu(a0 @ W1 + b1)
__device__ float g_pool[N_GRAPHS * HIDD];        // per-graph scatter accumulator
__device__ float g_cnt[N_GRAPHS];

// vectorized fire-and-forget global reduction (sm_90+)
__device__ __forceinline__ void red_add_v4(float* addr, float4 v) {
    asm volatile("red.global.add.v4.f32 [%0], {%1, %2, %3, %4};"
                 :: "l"(addr), "f"(v.x), "f"(v.y), "f"(v.z), "f"(v.w)
                 : "memory");
}

// ---------------- kernels ---------------------------------------------------

// deg = 1 (self loop), pool = 0, cnt = 0
__global__ void k_init() {
    int i = blockIdx.x * blockDim.x + threadIdx.x;
    if (i < N_NODES) g_deg[i] = 1.0f;
    if (i < N_GRAPHS * HIDD) g_pool[i] = 0.0f;
    if (i < N_GRAPHS) g_cnt[i] = 0.0f;
}

// deg[dst] += 1 over edges; cnt[batch[i]] += 1 over nodes
__global__ void k_counts(const int* __restrict__ ei, const int* __restrict__ batch) {
    int i = blockIdx.x * blockDim.x + threadIdx.x;
    if (i < N_EDGES) {
        atomicAdd(&g_deg[ei[N_EDGES + i]], 1.0f);
    } else {
        int j = i - N_EDGES;
        if (j < N_NODES) atomicAdd(&g_cnt[batch[j]], 1.0f);
    }
}

__global__ void k_dis() {
    int i = blockIdx.x * blockDim.x + threadIdx.x;
    if (i < N_NODES) g_dis[i] = rsqrtf(g_deg[i]);
}

// a0[i] = emb[x[i]] * dis[i]^2   (self-loop term; also initializes a0)
__global__ void k_self0(const int* __restrict__ x, const float* __restrict__ emb) {
    int t = blockIdx.x * blockDim.x + threadIdx.x;
    int node = t >> 5, lane = t & 31;
    if (node >= N_NODES) return;
    float d = g_dis[node];
    float n = d * d;
    float4 v = reinterpret_cast<const float4*>(emb)[(size_t)x[node] * 32 + lane];
    v.x *= n; v.y *= n; v.z *= n; v.w *= n;
    reinterpret_cast<float4*>(g_a0)[(size_t)node * 32 + lane] = v;
}

// a0[dst] += emb[x[src]] * dis[src]*dis[dst]
__global__ void k_edge0(const int* __restrict__ ei, const int* __restrict__ x,
                        const float* __restrict__ emb) {
    int t = blockIdx.x * blockDim.x + threadIdx.x;
    int e = t >> 5, lane = t & 31;
    if (e >= N_EDGES) return;
    int s = ei[e];
    int d = ei[N_EDGES + e];
    float nrm = g_dis[s] * g_dis[d];
    float4 v = reinterpret_cast<const float4*>(emb)[(size_t)x[s] * 32 + lane];
    v.x *= nrm; v.y *= nrm; v.z *= nrm; v.w *= nrm;
    red_add_v4(&g_a0[(size_t)d * 128 + lane * 4], v);
}

// h1 = relu(a0 @ W1 + b1), 32 rows per block, 256 threads
__global__ void k_gemm_relu(const float* __restrict__ W, const float* __restrict__ b) {
    extern __shared__ float sm[];
    float* sW = sm;            // 128*128 floats = 64 KB
    float* sA = sm + 16384;    // 32*128  floats = 16 KB
    int tid = threadIdx.x;

    const float4* W4 = reinterpret_cast<const float4*>(W);
    for (int i = tid; i < 4096; i += 256)
        reinterpret_cast<float4*>(sW)[i] = W4[i];

    int row0 = blockIdx.x * 32;
    const float4* A4 = reinterpret_cast<const float4*>(g_a0 + (size_t)row0 * 128);
    for (int i = tid; i < 1024; i += 256)
        reinterpret_cast<float4*>(sA)[i] = A4[i];
    __syncthreads();

    int warp = tid >> 5, lane = tid & 31;
    int r0 = warp * 4;

    float4 acc[4];
    #pragma unroll
    for (int r = 0; r < 4; r++) acc[r] = make_float4(0.f, 0.f, 0.f, 0.f);

    #pragma unroll 8
    for (int k = 0; k < 128; k++) {
        float4 w = reinterpret_cast<float4*>(sW + k * 128)[lane];
        #pragma unroll
        for (int r = 0; r < 4; r++) {
            float a = sA[(r0 + r) * 128 + k];
            acc[r].x += a * w.x;
            acc[r].y += a * w.y;
            acc[r].z += a * w.z;
            acc[r].w += a * w.w;
        }
    }

    float4 bb = reinterpret_cast<const float4*>(b)[lane];
    #pragma unroll
    for (int r = 0; r < 4; r++) {
        float4 o;
        o.x = fmaxf(acc[r].x + bb.x, 0.f);
        o.y = fmaxf(acc[r].y + bb.y, 0.f);
        o.z = fmaxf(acc[r].z + bb.z, 0.f);
        o.w = fmaxf(acc[r].w + bb.w, 0.f);
        reinterpret_cast<float4*>(g_h1 + (size_t)(row0 + r0 + r) * 128)[lane] = o;
    }
}

// pool[batch[i]] += h1[i] * dis[i]^2   (layer-2 self loop, pooled directly)
__global__ void k_self1(const int* __restrict__ batch) {
    int t = blockIdx.x * blockDim.x + threadIdx.x;
    int node = t >> 5, lane = t & 31;
    if (node >= N_NODES) return;
    float d = g_dis[node];
    float n = d * d;
    float4 v = reinterpret_cast<const float4*>(g_h1)[(size_t)node * 32 + lane];
    v.x *= n; v.y *= n; v.z *= n; v.w *= n;
    red_add_v4(&g_pool[batch[node] * 128 + lane * 4], v);
}

// pool[batch[dst]] += h1[src] * dis[src]*dis[dst]   (layer-2 edges, pooled directly)
__global__ void k_edge1(const int* __restrict__ ei, const int* __restrict__ batch) {
    int t = blockIdx.x * blockDim.x + threadIdx.x;
    int e = t >> 5, lane = t & 31;
    if (e >= N_EDGES) return;
    int s = ei[e];
    int d = ei[N_EDGES + e];
    float nrm = g_dis[s] * g_dis[d];
    float4 v = reinterpret_cast<const float4*>(g_h1)[(size_t)s * 32 + lane];
    v.x *= nrm; v.y *= nrm; v.z *= nrm; v.w *= nrm;
    red_add_v4(&g_pool[batch[d] * 128 + lane * 4], v);
}

// out[g] = (pool[g]/max(cnt,1)) @ W2 + b2   -- tiny 512x128x128 GEMM
__global__ void k_out(const float* __restrict__ W2, const float* __restrict__ b2,
                      float* __restrict__ out) {
    __shared__ float sp[128];
    int g = blockIdx.x, c = threadIdx.x;
    float inv = 1.0f / fmaxf(g_cnt[g], 1.0f);
    sp[c] = g_pool[g * 128 + c] * inv;
    __syncthreads();
    float acc = b2[c];
    #pragma unroll 8
    for (int k = 0; k < 128; k++)
        acc += sp[k] * W2[k * 128 + c];
    out[g * 128 + c] = acc;
}

// ---------------- launcher ---------------------------------------------------
extern "C" void kernel_launch(void* const* d_in, const int* in_sizes, int n_in,
                              void* d_out, int out_size) {
    const int*   x     = (const int*)d_in[0];
    const int*   ei    = (const int*)d_in[1];
    const int*   batch = (const int*)d_in[2];
    const float* emb   = (const float*)d_in[3];
    const float* W1    = (const float*)d_in[4];
    const float* b1    = (const float*)d_in[5];
    const float* W2    = (const float*)d_in[6];
    const float* b2    = (const float*)d_in[7];
    float* out = (float*)d_out;

    cudaFuncSetAttribute(k_gemm_relu, cudaFuncAttributeMaxDynamicSharedMemorySize,
                         (16384 + 4096) * sizeof(float));

    k_init  <<<(N_NODES + 255) / 256, 256>>>();
    k_counts<<<(N_EDGES + N_NODES + 255) / 256, 256>>>(ei, batch);
    k_dis   <<<(N_NODES + 255) / 256, 256>>>();
    k_self0 <<<(N_NODES * 32 + 255) / 256, 256>>>(x, emb);
    k_edge0 <<<(N_EDGES + 7) / 8, 256>>>(ei, x, emb);
    k_gemm_relu<<<N_NODES / 32, 256, (16384 + 4096) * sizeof(float)>>>(W1, b1);
    k_self1 <<<(N_NODES * 32 + 255) / 256, 256>>>(batch);
    k_edge1 <<<(N_EDGES + 7) / 8, 256>>>(ei, batch);
    k_out   <<<N_GRAPHS, 128>>>(W2, b2, out);
}

// round 6
// speedup vs baseline: 1.6629x; 1.6629x over previous
#include <cuda_runtime.h>
#include <cuda_bf16.h>

#define N_NODES  100000
#define N_EDGES  600000
#define N_GRAPHS 512
#define VOCABN   4096
#define EMBD     128
#define HIDD     128

// ---------------- scratch (device globals; no allocations allowed) ----------
__device__ float g_deg[N_NODES];
__device__ float g_dis[N_NODES];
__device__ float g_embW[(size_t)VOCABN * HIDD];  // emb @ W1 (precomputed, 2 MB)
__device__ float g_a0[(size_t)N_NODES * HIDD];   // agg of embW (pre-activation h1)
__device__ float g_pool[N_GRAPHS * HIDD];        // per-graph scatter accumulator
__device__ float g_cnt[N_GRAPHS];

// vectorized fire-and-forget global reduction (sm_90+)
__device__ __forceinline__ void red_add_v4(float* addr, float4 v) {
    asm volatile("red.global.add.v4.f32 [%0], {%1, %2, %3, %4};"
                 :: "l"(addr), "f"(v.x), "f"(v.y), "f"(v.z), "f"(v.w)
                 : "memory");
}

// ---------------- kernels ---------------------------------------------------

// deg = 1 (self loop), pool = 0, cnt = 0
__global__ void k_init() {
    int i = blockIdx.x * blockDim.x + threadIdx.x;
    if (i < N_NODES) g_deg[i] = 1.0f;
    if (i < N_GRAPHS * HIDD) g_pool[i] = 0.0f;
    if (i < N_GRAPHS) g_cnt[i] = 0.0f;
}

// deg[dst] += 1 over edges; cnt[batch[i]] += 1 over nodes
__global__ void k_counts(const int* __restrict__ ei, const int* __restrict__ batch) {
    int i = blockIdx.x * blockDim.x + threadIdx.x;
    if (i < N_EDGES) {
        atomicAdd(&g_deg[ei[N_EDGES + i]], 1.0f);
    } else {
        int j = i - N_EDGES;
        if (j < N_NODES) atomicAdd(&g_cnt[batch[j]], 1.0f);
    }
}

__global__ void k_dis() {
    int i = blockIdx.x * blockDim.x + threadIdx.x;
    if (i < N_NODES) g_dis[i] = rsqrtf(g_deg[i]);
}

// embW = emb @ W1  (4096 x 128 x 128, tiny). 32 rows per block, 256 threads.
__global__ void k_embW(const float* __restrict__ emb, const float* __restrict__ W) {
    extern __shared__ float sm[];
    float* sW = sm;            // 128*128 floats = 64 KB
    float* sA = sm + 16384;    // 32*128  floats = 16 KB
    int tid = threadIdx.x;

    const float4* W4 = reinterpret_cast<const float4*>(W);
    for (int i = tid; i < 4096; i += 256)
        reinterpret_cast<float4*>(sW)[i] = W4[i];

    int row0 = blockIdx.x * 32;
    const float4* A4 = reinterpret_cast<const float4*>(emb + (size_t)row0 * 128);
    for (int i = tid; i < 1024; i += 256)
        reinterpret_cast<float4*>(sA)[i] = A4[i];
    __syncthreads();

    int warp = tid >> 5, lane = tid & 31;
    int r0 = warp * 4;

    float4 acc[4];
    #pragma unroll
    for (int r = 0; r < 4; r++) acc[r] = make_float4(0.f, 0.f, 0.f, 0.f);

    #pragma unroll 8
    for (int k = 0; k < 128; k++) {
        float4 w = reinterpret_cast<float4*>(sW + k * 128)[lane];
        #pragma unroll
        for (int r = 0; r < 4; r++) {
            float a = sA[(r0 + r) * 128 + k];
            acc[r].x += a * w.x;
            acc[r].y += a * w.y;
            acc[r].z += a * w.z;
            acc[r].w += a * w.w;
        }
    }

    #pragma unroll
    for (int r = 0; r < 4; r++)
        reinterpret_cast<float4*>(g_embW + (size_t)(row0 + r0 + r) * 128)[lane] = acc[r];
}

// a0[i] = embW[x[i]] * dis[i]^2   (layer-1 self-loop term; initializes a0)
__global__ void k_self0(const int* __restrict__ x) {
    int t = blockIdx.x * blockDim.x + threadIdx.x;
    int node = t >> 5, lane = t & 31;
    if (node >= N_NODES) return;
    float d = g_dis[node];
    float n = d * d;
    float4 v = reinterpret_cast<const float4*>(g_embW)[(size_t)x[node] * 32 + lane];
    v.x *= n; v.y *= n; v.z *= n; v.w *= n;
    reinterpret_cast<float4*>(g_a0)[(size_t)node * 32 + lane] = v;
}

// a0[dst] += embW[x[src]] * dis[src]*dis[dst]
__global__ void k_edge0(const int* __restrict__ ei, const int* __restrict__ x) {
    int t = blockIdx.x * blockDim.x + threadIdx.x;
    int e = t >> 5, lane = t & 31;
    if (e >= N_EDGES) return;
    int s = ei[e];
    int d = ei[N_EDGES + e];
    float nrm = g_dis[s] * g_dis[d];
    float4 v = reinterpret_cast<const float4*>(g_embW)[(size_t)x[s] * 32 + lane];
    v.x *= nrm; v.y *= nrm; v.z *= nrm; v.w *= nrm;
    red_add_v4(&g_a0[(size_t)d * 128 + lane * 4], v);
}

// pool[batch[i]] += relu(a0[i]+b1) * dis[i]^2   (layer-2 self loop, pooled directly)
__global__ void k_self1(const int* __restrict__ batch, const float* __restrict__ b1) {
    int t = blockIdx.x * blockDim.x + threadIdx.x;
    int node = t >> 5, lane = t & 31;
    if (node >= N_NODES) return;
    float d = g_dis[node];
    float n = d * d;
    float4 bb = reinterpret_cast<const float4*>(b1)[lane];
    float4 v = reinterpret_cast<const float4*>(g_a0)[(size_t)node * 32 + lane];
    v.x = fmaxf(v.x + bb.x, 0.f) * n;
    v.y = fmaxf(v.y + bb.y, 0.f) * n;
    v.z = fmaxf(v.z + bb.z, 0.f) * n;
    v.w = fmaxf(v.w + bb.w, 0.f) * n;
    red_add_v4(&g_pool[batch[node] * 128 + lane * 4], v);
}

// pool[batch[dst]] += relu(a0[src]+b1) * dis[src]*dis[dst]
__global__ void k_edge1(const int* __restrict__ ei, const int* __restrict__ batch,
                        const float* __restrict__ b1) {
    int t = blockIdx.x * blockDim.x + threadIdx.x;
    int e = t >> 5, lane = t & 31;
    if (e >= N_EDGES) return;
    int s = ei[e];
    int d = ei[N_EDGES + e];
    float nrm = g_dis[s] * g_dis[d];
    float4 bb = reinterpret_cast<const float4*>(b1)[lane];
    float4 v = reinterpret_cast<const float4*>(g_a0)[(size_t)s * 32 + lane];
    v.x = fmaxf(v.x + bb.x, 0.f) * nrm;
    v.y = fmaxf(v.y + bb.y, 0.f) * nrm;
    v.z = fmaxf(v.z + bb.z, 0.f) * nrm;
    v.w = fmaxf(v.w + bb.w, 0.f) * nrm;
    red_add_v4(&g_pool[batch[d] * 128 + lane * 4], v);
}

// out[g] = (pool[g]/max(cnt,1)) @ W2 + b2   -- tiny 512x128x128 GEMM
__global__ void k_out(const float* __restrict__ W2, const float* __restrict__ b2,
                      float* __restrict__ out) {
    __shared__ float sp[128];
    int g = blockIdx.x, c = threadIdx.x;
    float inv = 1.0f / fmaxf(g_cnt[g], 1.0f);
    sp[c] = g_pool[g * 128 + c] * inv;
    __syncthreads();
    float acc = b2[c];
    #pragma unroll 8
    for (int k = 0; k < 128; k++)
        acc += sp[k] * W2[k * 128 + c];
    out[g * 128 + c] = acc;
}

// ---------------- launcher ---------------------------------------------------
extern "C" void kernel_launch(void* const* d_in, const int* in_sizes, int n_in,
                              void* d_out, int out_size) {
    const int*   x     = (const int*)d_in[0];
    const int*   ei    = (const int*)d_in[1];
    const int*   batch = (const int*)d_in[2];
    const float* emb   = (const float*)d_in[3];
    const float* W1    = (const float*)d_in[4];
    const float* b1    = (const float*)d_in[5];
    const float* W2    = (const float*)d_in[6];
    const float* b2    = (const float*)d_in[7];
    float* out = (float*)d_out;

    cudaFuncSetAttribute(k_embW, cudaFuncAttributeMaxDynamicSharedMemorySize,
                         (16384 + 4096) * sizeof(float));

    k_init  <<<(N_NODES + 255) / 256, 256>>>();
    k_counts<<<(N_EDGES + N_NODES + 255) / 256, 256>>>(ei, batch);
    k_embW  <<<VOCABN / 32, 256, (16384 + 4096) * sizeof(float)>>>(emb, W1);
    k_dis   <<<(N_NODES + 255) / 256, 256>>>();
    k_self0 <<<(N_NODES * 32 + 255) / 256, 256>>>(x);
    k_edge0 <<<(N_EDGES + 7) / 8, 256>>>(ei, x);
    k_self1 <<<(N_NODES * 32 + 255) / 256, 256>>>(batch, b1);
    k_edge1 <<<(N_EDGES + 7) / 8, 256>>>(ei, batch, b1);
    k_out   <<<N_GRAPHS, 128>>>(W2, b2, out);
}

// round 9
// speedup vs baseline: 2.0322x; 1.2221x over previous
#include <cuda_runtime.h>
#include <cuda_bf16.h>

#define N_NODES  100000
#define N_EDGES  600000
#define N_GRAPHS 512
#define VOCABN   4096
#define EMBD     128
#define HIDD     128
#define SCAN_BLOCKS ((N_NODES + 255) / 256)   // 391

// ---------------- scratch (device globals) ----------------------------------
__device__ float g_dis[N_NODES];
__device__ float g_embW[(size_t)VOCABN * HIDD];  // emb @ W1 (2 MB, L2-resident)
__device__ float g_a0[(size_t)N_NODES * HIDD];   // aggregated pre-activation h1
__device__ float g_pool[N_GRAPHS * HIDD];
__device__ float g_cnt[N_GRAPHS];
__device__ int   g_rp[N_NODES + 1];              // CSR row pointer (by dst)
__device__ int   g_cur[N_NODES];                 // counts, then scatter cursor
__device__ int   g_bsum[512];                    // scan block sums
__device__ int   g_csrc[N_EDGES];                // edge sources grouped by dst

__device__ __forceinline__ void red_add_v4(float* addr, float4 v) {
    asm volatile("red.global.add.v4.f32 [%0], {%1, %2, %3, %4};"
                 :: "l"(addr), "f"(v.x), "f"(v.y), "f"(v.z), "f"(v.w)
                 : "memory");
}

// ---------------- kernels ---------------------------------------------------

__global__ void k_zero() {
    int i = blockIdx.x * blockDim.x + threadIdx.x;
    if (i < N_NODES) g_cur[i] = 0;
    if (i < N_GRAPHS * HIDD) g_pool[i] = 0.0f;
    if (i < N_GRAPHS) g_cnt[i] = 0.0f;
}

// in-degree histogram over edges; graph node-count histogram
__global__ void k_count(const int* __restrict__ ei, const int* __restrict__ batch) {
    int i = blockIdx.x * blockDim.x + threadIdx.x;
    if (i < N_EDGES) {
        atomicAdd(&g_cur[ei[N_EDGES + i]], 1);
    } else {
        int j = i - N_EDGES;
        if (j < N_NODES) atomicAdd(&g_cnt[batch[j]], 1.0f);
    }
}

// block-local exclusive scan of counts -> g_rp, block totals -> g_bsum.
// Also computes dis = rsqrt(1 + in_count) for free.
__global__ void k_scan1() {
    __shared__ int sh[256];
    int tid = threadIdx.x;
    int i = blockIdx.x * 256 + tid;
    int c = (i < N_NODES) ? g_cur[i] : 0;
    if (i < N_NODES) g_dis[i] = rsqrtf(1.0f + (float)c);
    sh[tid] = c;
    __syncthreads();
    #pragma unroll
    for (int ofs = 1; ofs < 256; ofs <<= 1) {
        int v = (tid >= ofs) ? sh[tid - ofs] : 0;
        __syncthreads();
        sh[tid] += v;
        __syncthreads();
    }
    if (i < N_NODES) g_rp[i] = sh[tid] - c;       // exclusive within block
    if (tid == 255) g_bsum[blockIdx.x] = sh[255];
}

// exclusive scan of block sums (single block, 512 threads >= 391 blocks)
__global__ void k_scan2() {
    __shared__ int sh[512];
    int tid = threadIdx.x;
    int c = (tid < SCAN_BLOCKS) ? g_bsum[tid] : 0;
    sh[tid] = c;
    __syncthreads();
    #pragma unroll
    for (int ofs = 1; ofs < 512; ofs <<= 1) {
        int v = (tid >= ofs) ? sh[tid - ofs] : 0;
        __syncthreads();
        sh[tid] += v;
        __syncthreads();
    }
    g_bsum[tid] = sh[tid] - c;                    // exclusive
}

// finalize row pointers and init cursors
__global__ void k_scan3() {
    int i = blockIdx.x * blockDim.x + threadIdx.x;
    if (i < N_NODES) {
        int v = g_rp[i] + g_bsum[blockIdx.x * 256 / 256 == 0 ? 0 : 0];  // placeholder
        v = g_rp[i] + g_bsum[i >> 8];
        g_rp[i] = v;
        g_cur[i] = v;
    }
    if (i == 0) g_rp[N_NODES] = N_EDGES;
}

// bucket edge sources by dst
__global__ void k_scatter(const int* __restrict__ ei) {
    int e = blockIdx.x * blockDim.x + threadIdx.x;
    if (e >= N_EDGES) return;
    int s = ei[e];
    int d = ei[N_EDGES + e];
    int pos = atomicAdd(&g_cur[d], 1);
    g_csrc[pos] = s;
}

// embW = emb @ W1 (4096 x 128 x 128)
__global__ void k_embW(const float* __restrict__ emb, const float* __restrict__ W) {
    extern __shared__ float sm[];
    float* sW = sm;            // 64 KB
    float* sA = sm + 16384;    // 16 KB
    int tid = threadIdx.x;

    const float4* W4 = reinterpret_cast<const float4*>(W);
    for (int i = tid; i < 4096; i += 256)
        reinterpret_cast<float4*>(sW)[i] = W4[i];

    int row0 = blockIdx.x * 32;
    const float4* A4 = reinterpret_cast<const float4*>(emb + (size_t)row0 * 128);
    for (int i = tid; i < 1024; i += 256)
        reinterpret_cast<float4*>(sA)[i] = A4[i];
    __syncthreads();

    int warp = tid >> 5, lane = tid & 31;
    int r0 = warp * 4;
    float4 acc[4];
    #pragma unroll
    for (int r = 0; r < 4; r++) acc[r] = make_float4(0.f, 0.f, 0.f, 0.f);

    #pragma unroll 8
    for (int k = 0; k < 128; k++) {
        float4 w = reinterpret_cast<float4*>(sW + k * 128)[lane];
        #pragma unroll
        for (int r = 0; r < 4; r++) {
            float a = sA[(r0 + r) * 128 + k];
            acc[r].x += a * w.x;
            acc[r].y += a * w.y;
            acc[r].z += a * w.z;
            acc[r].w += a * w.w;
        }
    }
    #pragma unroll
    for (int r = 0; r < 4; r++)
        reinterpret_cast<float4*>(g_embW + (size_t)(row0 + r0 + r) * 128)[lane] = acc[r];
}

// layer-1 aggregation, gather form: warp per dst node.
// a0[d] = dis[d] * ( dis[d]*embW[x[d]] + sum_in dis[s]*embW[x[s]] )
__global__ void k_agg0(const int* __restrict__ x) {
    int t = blockIdx.x * blockDim.x + threadIdx.x;
    int d = t >> 5, lane = t & 31;
    if (d >= N_NODES) return;
    const float4* E4 = reinterpret_cast<const float4*>(g_embW);

    float dd = g_dis[d];
    float4 e = E4[(size_t)x[d] * 32 + lane];
    float4 acc;
    acc.x = dd * e.x; acc.y = dd * e.y; acc.z = dd * e.z; acc.w = dd * e.w;

    int j = g_rp[d], jend = g_rp[d + 1];
    for (; j < jend; j++) {
        int s = g_csrc[j];
        float ds = g_dis[s];
        float4 v = E4[(size_t)x[s] * 32 + lane];
        acc.x += ds * v.x; acc.y += ds * v.y;
        acc.z += ds * v.z; acc.w += ds * v.w;
    }
    acc.x *= dd; acc.y *= dd; acc.z *= dd; acc.w *= dd;
    reinterpret_cast<float4*>(g_a0)[(size_t)d * 32 + lane] = acc;
}

// layer-2 aggregation + pooling, gather form: warp per dst node.
// pool[batch[d]] += dis[d] * ( dis[d]*r[d] + sum_in dis[s]*r[s] ),
// r[i] = relu(a0[i] + b1)
__global__ void k_agg1(const int* __restrict__ batch, const float* __restrict__ b1) {
    int t = blockIdx.x * blockDim.x + threadIdx.x;
    int d = t >> 5, lane = t & 31;
    if (d >= N_NODES) return;
    const float4* A4 = reinterpret_cast<const float4*>(g_a0);
    float4 bb = reinterpret_cast<const float4*>(b1)[lane];

    float dd = g_dis[d];
    float4 a = A4[(size_t)d * 32 + lane];
    float4 acc;
    acc.x = dd * fmaxf(a.x + bb.x, 0.f);
    acc.y = dd * fmaxf(a.y + bb.y, 0.f);
    acc.z = dd * fmaxf(a.z + bb.z, 0.f);
    acc.w = dd * fmaxf(a.w + bb.w, 0.f);

    int j = g_rp[d], jend = g_rp[d + 1];
    for (; j < jend; j++) {
        int s = g_csrc[j];
        float ds = g_dis[s];
        float4 v = A4[(size_t)s * 32 + lane];
        acc.x += ds * fmaxf(v.x + bb.x, 0.f);
        acc.y += ds * fmaxf(v.y + bb.y, 0.f);
        acc.z += ds * fmaxf(v.z + bb.z, 0.f);
        acc.w += ds * fmaxf(v.w + bb.w, 0.f);
    }
    acc.x *= dd; acc.y *= dd; acc.z *= dd; acc.w *= dd;
    red_add_v4(&g_pool[batch[d] * 128 + lane * 4], acc);
}

// out[g] = (pool[g]/max(cnt,1)) @ W2 + b2
__global__ void k_out(const float* __restrict__ W2, const float* __restrict__ b2,
                      float* __restrict__ out) {
    __shared__ float sp[128];
    int g = blockIdx.x, c = threadIdx.x;
    float inv = 1.0f / fmaxf(g_cnt[g], 1.0f);
    sp[c] = g_pool[g * 128 + c] * inv;
    __syncthreads();
    float acc = b2[c];
    #pragma unroll 8
    for (int k = 0; k < 128; k++)
        acc += sp[k] * W2[k * 128 + c];
    out[g * 128 + c] = acc;
}

// ---------------- launcher ---------------------------------------------------
extern "C" void kernel_launch(void* const* d_in, const int* in_sizes, int n_in,
                              void* d_out, int out_size) {
    const int*   x     = (const int*)d_in[0];
    const int*   ei    = (const int*)d_in[1];
    const int*   batch = (const int*)d_in[2];
    const float* emb   = (const float*)d_in[3];
    const float* W1    = (const float*)d_in[4];
    const float* b1    = (const float*)d_in[5];
    const float* W2    = (const float*)d_in[6];
    const float* b2    = (const float*)d_in[7];
    float* out = (float*)d_out;

    cudaFuncSetAttribute(k_embW, cudaFuncAttributeMaxDynamicSharedMemorySize,
                         (16384 + 4096) * sizeof(float));

    k_zero   <<<(N_NODES + 255) / 256, 256>>>();
    k_count  <<<(N_EDGES + N_NODES + 255) / 256, 256>>>(ei, batch);
    k_scan1  <<<SCAN_BLOCKS, 256>>>();
    k_scan2  <<<1, 512>>>();
    k_scan3  <<<SCAN_BLOCKS, 256>>>();
    k_scatter<<<(N_EDGES + 255) / 256, 256>>>(ei);
    k_embW   <<<VOCABN / 32, 256, (16384 + 4096) * sizeof(float)>>>(emb, W1);
    k_agg0   <<<(N_NODES * 32 + 255) / 256, 256>>>(x);
    k_agg1   <<<(N_NODES * 32 + 255) / 256, 256>>>(batch, b1);
    k_out    <<<N_GRAPHS, 128>>>(W2, b2, out);
}

// round 11
// speedup vs baseline: 2.8846x; 1.4195x over previous
#include <cuda_runtime.h>
#include <cuda_fp16.h>
#include <cuda_bf16.h>

#define N_NODES  100000
#define N_EDGES  600000
#define N_GRAPHS 512
#define VOCABN   4096
#define EMBD     128
#define HIDD     128
#define SCAN_BLOCKS ((N_NODES + 255) / 256)   // 391

// ---------------- scratch (device globals) ----------------------------------
__device__ float g_dis[N_NODES];
__device__ uint2 g_embWh[(size_t)VOCABN * 32];   // emb @ W1, fp16 (1 MB): 32 uint2/row
__device__ uint2 g_rh[(size_t)N_NODES * 32];     // relu(a0+b1)*dis, fp16 (25 MB)
__device__ float g_pool[N_GRAPHS * HIDD];
__device__ float g_cnt[N_GRAPHS];
__device__ int   g_rp[N_NODES + 1];              // CSR row pointer (by dst)
__device__ int   g_cur[N_NODES];                 // counts, then scatter cursor
__device__ int   g_bsum[512];                    // scan block sums
__device__ int   g_csrc[N_EDGES];                // edge sources grouped by dst

__device__ __forceinline__ void red_add_v4(float* addr, float4 v) {
    asm volatile("red.global.add.v4.f32 [%0], {%1, %2, %3, %4};"
                 :: "l"(addr), "f"(v.x), "f"(v.y), "f"(v.z), "f"(v.w)
                 : "memory");
}

__device__ __forceinline__ uint2 pack_h4(float4 v) {
    __half2 a = __floats2half2_rn(v.x, v.y);
    __half2 b = __floats2half2_rn(v.z, v.w);
    uint2 r;
    r.x = *reinterpret_cast<unsigned*>(&a);
    r.y = *reinterpret_cast<unsigned*>(&b);
    return r;
}
__device__ __forceinline__ float4 unpack_h4(uint2 r) {
    float2 a = __half22float2(*reinterpret_cast<__half2*>(&r.x));
    float2 b = __half22float2(*reinterpret_cast<__half2*>(&r.y));
    return make_float4(a.x, a.y, b.x, b.y);
}

__device__ __forceinline__ int warp_incl_scan(int v, int lane) {
    #pragma unroll
    for (int o = 1; o < 32; o <<= 1) {
        int n = __shfl_up_sync(0xffffffffu, v, o);
        if (lane >= o) v += n;
    }
    return v;
}

// ---------------- kernels ---------------------------------------------------

__global__ void k_zero() {
    int i = blockIdx.x * blockDim.x + threadIdx.x;
    if (i < N_NODES) g_cur[i] = 0;
    if (i < N_GRAPHS * HIDD) g_pool[i] = 0.0f;
    if (i < N_GRAPHS) g_cnt[i] = 0.0f;
}

// in-degree histogram over edges; graph node-count histogram
__global__ void k_count(const int* __restrict__ ei, const int* __restrict__ batch) {
    int i = blockIdx.x * blockDim.x + threadIdx.x;
    if (i < N_EDGES) {
        atomicAdd(&g_cur[ei[N_EDGES + i]], 1);
    } else {
        int j = i - N_EDGES;
        if (j < N_NODES) atomicAdd(&g_cnt[batch[j]], 1.0f);
    }
}

// block-local exclusive scan (shuffle-based) -> g_rp, block totals -> g_bsum.
// Also computes dis = rsqrt(1 + in_count).
__global__ void k_scan1() {
    __shared__ int ws[8];
    int tid = threadIdx.x, lane = tid & 31, w = tid >> 5;
    int i = blockIdx.x * 256 + tid;
    int c = (i < N_NODES) ? g_cur[i] : 0;
    if (i < N_NODES) g_dis[i] = rsqrtf(1.0f + (float)c);
    int s = warp_incl_scan(c, lane);
    if (lane == 31) ws[w] = s;
    __syncthreads();
    if (w == 0) {
        int v = (lane < 8) ? ws[lane] : 0;
        v = warp_incl_scan(v, lane);
        if (lane < 8) ws[lane] = v;
    }
    __syncthreads();
    int excl = s - c + (w > 0 ? ws[w - 1] : 0);
    if (i < N_NODES) g_rp[i] = excl;
    if (tid == 255) g_bsum[blockIdx.x] = ws[7];
}

// exclusive scan of block sums (single block, 512 threads >= 391 blocks)
__global__ void k_scan2() {
    __shared__ int ws[16];
    int tid = threadIdx.x, lane = tid & 31, w = tid >> 5;
    int c = (tid < SCAN_BLOCKS) ? g_bsum[tid] : 0;
    int s = warp_incl_scan(c, lane);
    if (lane == 31) ws[w] = s;
    __syncthreads();
    if (w == 0) {
        int v = (lane < 16) ? ws[lane] : 0;
        v = warp_incl_scan(v, lane);
        if (lane < 16) ws[lane] = v;
    }
    __syncthreads();
    g_bsum[tid] = s - c + (w > 0 ? ws[w - 1] : 0);
}

// finalize row pointers and init cursors
__global__ void k_scan3() {
    int i = blockIdx.x * blockDim.x + threadIdx.x;
    if (i < N_NODES) {
        int v = g_rp[i] + g_bsum[i >> 8];
        g_rp[i] = v;
        g_cur[i] = v;
    }
    if (i == 0) g_rp[N_NODES] = N_EDGES;
}

// bucket edge sources by dst
__global__ void k_scatter(const int* __restrict__ ei) {
    int e = blockIdx.x * blockDim.x + threadIdx.x;
    if (e >= N_EDGES) return;
    int s = ei[e];
    int d = ei[N_EDGES + e];
    int pos = atomicAdd(&g_cur[d], 1);
    g_csrc[pos] = s;
}

// embW = emb @ W1 (4096 x 128 x 128), output fp16
__global__ void k_embW(const float* __restrict__ emb, const float* __restrict__ W) {
    extern __shared__ float sm[];
    float* sW = sm;            // 64 KB
    float* sA = sm + 16384;    // 16 KB
    int tid = threadIdx.x;

    const float4* W4 = reinterpret_cast<const float4*>(W);
    for (int i = tid; i < 4096; i += 256)
        reinterpret_cast<float4*>(sW)[i] = W4[i];

    int row0 = blockIdx.x * 32;
    const float4* A4 = reinterpret_cast<const float4*>(emb + (size_t)row0 * 128);
    for (int i = tid; i < 1024; i += 256)
        reinterpret_cast<float4*>(sA)[i] = A4[i];
    __syncthreads();

    int warp = tid >> 5, lane = tid & 31;
    int r0 = warp * 4;
    float4 acc[4];
    #pragma unroll
    for (int r = 0; r < 4; r++) acc[r] = make_float4(0.f, 0.f, 0.f, 0.f);

    #pragma unroll 8
    for (int k = 0; k < 128; k++) {
        float4 w = reinterpret_cast<float4*>(sW + k * 128)[lane];
        #pragma unroll
        for (int r = 0; r < 4; r++) {
            float a = sA[(r0 + r) * 128 + k];
            acc[r].x += a * w.x;
            acc[r].y += a * w.y;
            acc[r].z += a * w.z;
            acc[r].w += a * w.w;
        }
    }
    #pragma unroll
    for (int r = 0; r < 4; r++)
        g_embWh[(size_t)(row0 + r0 + r) * 32 + lane] = pack_h4(acc[r]);
}

// layer-1 aggregation (gather form), warp per dst node, fused bias+relu+dis:
// a0[d] = dis[d] * ( dis[d]*embW[x[d]] + sum_in dis[s]*embW[x[s]] )
// r[d]  = relu(a0[d] + b1) * dis[d]          (stored fp16)
__global__ void k_agg0(const int* __restrict__ x, const float* __restrict__ b1) {
    int t = blockIdx.x * blockDim.x + threadIdx.x;
    int d = t >> 5, lane = t & 31;
    if (d >= N_NODES) return;

    float dd = g_dis[d];
    float4 e = unpack_h4(g_embWh[(size_t)x[d] * 32 + lane]);
    float4 acc;
    acc.x = dd * e.x; acc.y = dd * e.y; acc.z = dd * e.z; acc.w = dd * e.w;

    int j = g_rp[d], jend = g_rp[d + 1];
    for (; j < jend; j++) {
        int s = g_csrc[j];
        float ds = g_dis[s];
        float4 v = unpack_h4(g_embWh[(size_t)x[s] * 32 + lane]);
        acc.x += ds * v.x; acc.y += ds * v.y;
        acc.z += ds * v.z; acc.w += ds * v.w;
    }

    float4 bb = reinterpret_cast<const float4*>(b1)[lane];
    float4 r;
    r.x = fmaxf(dd * acc.x + bb.x, 0.f) * dd;
    r.y = fmaxf(dd * acc.y + bb.y, 0.f) * dd;
    r.z = fmaxf(dd * acc.z + bb.z, 0.f) * dd;
    r.w = fmaxf(dd * acc.w + bb.w, 0.f) * dd;
    g_rh[(size_t)d * 32 + lane] = pack_h4(r);
}

// layer-2 aggregation + pooling (gather form), warp per dst node:
// pool[batch[d]] += dis[d] * ( r[d] + sum_in r[s] )
__global__ void k_agg1(const int* __restrict__ batch) {
    int t = blockIdx.x * blockDim.x + threadIdx.x;
    int d = t >> 5, lane = t & 31;
    if (d >= N_NODES) return;

    float4 acc = unpack_h4(g_rh[(size_t)d * 32 + lane]);

    int j = g_rp[d], jend = g_rp[d + 1];
    for (; j < jend; j++) {
        int s = g_csrc[j];
        float4 v = unpack_h4(g_rh[(size_t)s * 32 + lane]);
        acc.x += v.x; acc.y += v.y; acc.z += v.z; acc.w += v.w;
    }
    float dd = g_dis[d];
    acc.x *= dd; acc.y *= dd; acc.z *= dd; acc.w *= dd;
    red_add_v4(&g_pool[batch[d] * 128 + lane * 4], acc);
}

// out[g] = (pool[g]/max(cnt,1)) @ W2 + b2
__global__ void k_out(const float* __restrict__ W2, const float* __restrict__ b2,
                      float* __restrict__ out) {
    __shared__ float sp[128];
    int g = blockIdx.x, c = threadIdx.x;
    float inv = 1.0f / fmaxf(g_cnt[g], 1.0f);
    sp[c] = g_pool[g * 128 + c] * inv;
    __syncthreads();
    float acc = b2[c];
    #pragma unroll 8
    for (int k = 0; k < 128; k++)
        acc += sp[k] * W2[k * 128 + c];
    out[g * 128 + c] = acc;
}

// ---------------- launcher ---------------------------------------------------
extern "C" void kernel_launch(void* const* d_in, const int* in_sizes, int n_in,
                              void* d_out, int out_size) {
    const int*   x     = (const int*)d_in[0];
    const int*   ei    = (const int*)d_in[1];
    const int*   batch = (const int*)d_in[2];
    const float* emb   = (const float*)d_in[3];
    const float* W1    = (const float*)d_in[4];
    const float* b1    = (const float*)d_in[5];
    const float* W2    = (const float*)d_in[6];
    const float* b2    = (const float*)d_in[7];
    float* out = (float*)d_out;

    cudaFuncSetAttribute(k_embW, cudaFuncAttributeMaxDynamicSharedMemorySize,
                         (16384 + 4096) * sizeof(float));

    k_zero   <<<(N_NODES + 255) / 256, 256>>>();
    k_count  <<<(N_EDGES + N_NODES + 255) / 256, 256>>>(ei, batch);
    k_scan1  <<<SCAN_BLOCKS, 256>>>();
    k_scan2  <<<1, 512>>>();
    k_scan3  <<<SCAN_BLOCKS, 256>>>();
    k_scatter<<<(N_EDGES + 255) / 256, 256>>>(ei);
    k_embW   <<<VOCABN / 32, 256, (16384 + 4096) * sizeof(float)>>>(emb, W1);
    k_agg0   <<<(N_NODES * 32 + 255) / 256, 256>>>(x, b1);
    k_agg1   <<<(N_NODES * 32 + 255) / 256, 256>>>(batch);
    k_out    <<<N_GRAPHS, 128>>>(W2, b2, out);
}

// round 12
// speedup vs baseline: 2.9213x; 1.0127x over previous
#include <cuda_runtime.h>
#include <cuda_fp16.h>
#include <cuda_bf16.h>

#define N_NODES  100000
#define N_EDGES  600000
#define N_GRAPHS 512
#define VOCABN   4096
#define EMBD     128
#define HIDD     128
#define SCAN_BLOCKS ((N_NODES + 255) / 256)   // 391
#define EMBW_BLOCKS (VOCABN / 32)             // 128

// ---------------- scratch (device globals) ----------------------------------
__device__ float g_dis[N_NODES];
__device__ uint2 g_embWh[(size_t)VOCABN * 32];   // emb @ W1, fp16 (1 MB)
__device__ uint2 g_rh[(size_t)N_NODES * 32];     // relu(a0+b1)*dis, fp16 (25 MB)
__device__ float g_pool[N_GRAPHS * HIDD];
__device__ float g_cnt[N_GRAPHS];
__device__ int   g_rp[N_NODES + 1];              // CSR row pointer (by dst)
__device__ int   g_cur[N_NODES];                 // counts, then scatter cursor
__device__ int   g_bsum[512];                    // scan block sums
__device__ int   g_csrc[N_EDGES];                // edge sources grouped by dst

__device__ __forceinline__ void red_add_v4(float* addr, float4 v) {
    asm volatile("red.global.add.v4.f32 [%0], {%1, %2, %3, %4};"
                 :: "l"(addr), "f"(v.x), "f"(v.y), "f"(v.z), "f"(v.w)
                 : "memory");
}

__device__ __forceinline__ uint2 pack_h4(float4 v) {
    __half2 a = __floats2half2_rn(v.x, v.y);
    __half2 b = __floats2half2_rn(v.z, v.w);
    uint2 r;
    r.x = *reinterpret_cast<unsigned*>(&a);
    r.y = *reinterpret_cast<unsigned*>(&b);
    return r;
}
__device__ __forceinline__ float4 unpack_h4(uint2 r) {
    float2 a = __half22float2(*reinterpret_cast<__half2*>(&r.x));
    float2 b = __half22float2(*reinterpret_cast<__half2*>(&r.y));
    return make_float4(a.x, a.y, b.x, b.y);
}

__device__ __forceinline__ int warp_incl_scan(int v, int lane) {
    #pragma unroll
    for (int o = 1; o < 32; o <<= 1) {
        int n = __shfl_up_sync(0xffffffffu, v, o);
        if (lane >= o) v += n;
    }
    return v;
}

// ---------------- kernels ---------------------------------------------------

__global__ void k_zero() {
    int i = blockIdx.x * blockDim.x + threadIdx.x;
    if (i < N_NODES) g_cur[i] = 0;
    if (i < N_GRAPHS * HIDD) g_pool[i] = 0.0f;
    if (i < N_GRAPHS) g_cnt[i] = 0.0f;
}

// in-degree histogram over edges; graph node-count histogram
__global__ void k_count(const int* __restrict__ ei, const int* __restrict__ batch) {
    int i = blockIdx.x * blockDim.x + threadIdx.x;
    if (i < N_EDGES) {
        atomicAdd(&g_cur[ei[N_EDGES + i]], 1);
    } else {
        int j = i - N_EDGES;
        if (j < N_NODES) atomicAdd(&g_cnt[batch[j]], 1.0f);
    }
}

// block-local exclusive scan (shuffle) -> g_rp partial, totals -> g_bsum,
// dis = rsqrt(1 + in_count).
__global__ void k_scan1() {
    __shared__ int ws[8];
    int tid = threadIdx.x, lane = tid & 31, w = tid >> 5;
    int i = blockIdx.x * 256 + tid;
    int c = (i < N_NODES) ? g_cur[i] : 0;
    if (i < N_NODES) g_dis[i] = rsqrtf(1.0f + (float)c);
    int s = warp_incl_scan(c, lane);
    if (lane == 31) ws[w] = s;
    __syncthreads();
    if (w == 0) {
        int v = (lane < 8) ? ws[lane] : 0;
        v = warp_incl_scan(v, lane);
        if (lane < 8) ws[lane] = v;
    }
    __syncthreads();
    int excl = s - c + (w > 0 ? ws[w - 1] : 0);
    if (i < N_NODES) g_rp[i] = excl;
    if (tid == 255) g_bsum[blockIdx.x] = ws[7];
}

// Fused kernel: blocks [0, SCAN_BLOCKS) finalize CSR row pointers (computing
// their own block-sum prefix); blocks [SCAN_BLOCKS, +EMBW_BLOCKS) compute
// embW = emb @ W1 in fp16. The two halves are independent and overlap.
__global__ void k_fuse(const float* __restrict__ emb, const float* __restrict__ W) {
    extern __shared__ float sm[];
    int tid = threadIdx.x;

    if (blockIdx.x < SCAN_BLOCKS) {
        // ---- CSR finalize ----
        __shared__ int wred[8];
        int bid = blockIdx.x, lane = tid & 31, w = tid >> 5;
        int acc = 0;
        for (int j = tid; j < bid; j += 256) acc += g_bsum[j];
        #pragma unroll
        for (int o = 16; o > 0; o >>= 1)
            acc += __shfl_down_sync(0xffffffffu, acc, o);
        if (lane == 0) wred[w] = acc;
        __syncthreads();
        __shared__ int s_off;
        if (tid == 0) {
            int t = 0;
            #pragma unroll
            for (int k = 0; k < 8; k++) t += wred[k];
            s_off = t;
        }
        __syncthreads();
        int i = bid * 256 + tid;
        if (i < N_NODES) {
            int v = g_rp[i] + s_off;
            g_rp[i] = v;
            g_cur[i] = v;
        }
        if (bid == 0 && tid == 0) g_rp[N_NODES] = N_EDGES;
        return;
    }

    // ---- embW = emb @ W1 (fp16 out) ----
    float* sW = sm;            // 64 KB
    float* sA = sm + 16384;    // 16 KB

    const float4* W4 = reinterpret_cast<const float4*>(W);
    for (int i = tid; i < 4096; i += 256)
        reinterpret_cast<float4*>(sW)[i] = W4[i];

    int row0 = (blockIdx.x - SCAN_BLOCKS) * 32;
    const float4* A4 = reinterpret_cast<const float4*>(emb + (size_t)row0 * 128);
    for (int i = tid; i < 1024; i += 256)
        reinterpret_cast<float4*>(sA)[i] = A4[i];
    __syncthreads();

    int warp = tid >> 5, lane = tid & 31;
    int r0 = warp * 4;
    float4 acc[4];
    #pragma unroll
    for (int r = 0; r < 4; r++) acc[r] = make_float4(0.f, 0.f, 0.f, 0.f);

    #pragma unroll 8
    for (int k = 0; k < 128; k++) {
        float4 w = reinterpret_cast<float4*>(sW + k * 128)[lane];
        #pragma unroll
        for (int r = 0; r < 4; r++) {
            float a = sA[(r0 + r) * 128 + k];
            acc[r].x += a * w.x;
            acc[r].y += a * w.y;
            acc[r].z += a * w.z;
            acc[r].w += a * w.w;
        }
    }
    #pragma unroll
    for (int r = 0; r < 4; r++)
        g_embWh[(size_t)(row0 + r0 + r) * 32 + lane] = pack_h4(acc[r]);
}

// bucket edge sources by dst
__global__ void k_scatter(const int* __restrict__ ei) {
    int e = blockIdx.x * blockDim.x + threadIdx.x;
    if (e >= N_EDGES) return;
    int s = ei[e];
    int d = ei[N_EDGES + e];
    int pos = atomicAdd(&g_cur[d], 1);
    g_csrc[pos] = s;
}

// layer-1 aggregation (gather form), warp per dst node, fused bias+relu+dis:
// r[d] = relu( dis[d]*(dis[d]*embW[x[d]] + sum_in dis[s]*embW[x[s]]) + b1 ) * dis[d]
__global__ void k_agg0(const int* __restrict__ x, const float* __restrict__ b1) {
    int t = blockIdx.x * blockDim.x + threadIdx.x;
    int d = t >> 5, lane = t & 31;
    if (d >= N_NODES) return;

    float dd = g_dis[d];
    float4 e = unpack_h4(g_embWh[(size_t)x[d] * 32 + lane]);
    float4 acc;
    acc.x = dd * e.x; acc.y = dd * e.y; acc.z = dd * e.z; acc.w = dd * e.w;

    int j = g_rp[d], jend = g_rp[d + 1];
    for (; j + 1 < jend; j += 2) {
        int s0 = g_csrc[j], s1 = g_csrc[j + 1];
        float d0 = g_dis[s0], d1 = g_dis[s1];
        float4 v0 = unpack_h4(g_embWh[(size_t)x[s0] * 32 + lane]);
        float4 v1 = unpack_h4(g_embWh[(size_t)x[s1] * 32 + lane]);
        acc.x += d0 * v0.x + d1 * v1.x;
        acc.y += d0 * v0.y + d1 * v1.y;
        acc.z += d0 * v0.z + d1 * v1.z;
        acc.w += d0 * v0.w + d1 * v1.w;
    }
    if (j < jend) {
        int s = g_csrc[j];
        float ds = g_dis[s];
        float4 v = unpack_h4(g_embWh[(size_t)x[s] * 32 + lane]);
        acc.x += ds * v.x; acc.y += ds * v.y;
        acc.z += ds * v.z; acc.w += ds * v.w;
    }

    float4 bb = reinterpret_cast<const float4*>(b1)[lane];
    float4 r;
    r.x = fmaxf(dd * acc.x + bb.x, 0.f) * dd;
    r.y = fmaxf(dd * acc.y + bb.y, 0.f) * dd;
    r.z = fmaxf(dd * acc.z + bb.z, 0.f) * dd;
    r.w = fmaxf(dd * acc.w + bb.w, 0.f) * dd;
    g_rh[(size_t)d * 32 + lane] = pack_h4(r);
}

// layer-2 aggregation + pooling (gather form), warp per dst node:
// pool[batch[d]] += dis[d] * ( r[d] + sum_in r[s] )
__global__ void k_agg1(const int* __restrict__ batch) {
    int t = blockIdx.x * blockDim.x + threadIdx.x;
    int d = t >> 5, lane = t & 31;
    if (d >= N_NODES) return;

    float4 acc = unpack_h4(g_rh[(size_t)d * 32 + lane]);

    int j = g_rp[d], jend = g_rp[d + 1];
    for (; j + 1 < jend; j += 2) {
        int s0 = g_csrc[j], s1 = g_csrc[j + 1];
        float4 v0 = unpack_h4(g_rh[(size_t)s0 * 32 + lane]);
        float4 v1 = unpack_h4(g_rh[(size_t)s1 * 32 + lane]);
        acc.x += v0.x + v1.x; acc.y += v0.y + v1.y;
        acc.z += v0.z + v1.z; acc.w += v0.w + v1.w;
    }
    if (j < jend) {
        float4 v = unpack_h4(g_rh[(size_t)g_csrc[j] * 32 + lane]);
        acc.x += v.x; acc.y += v.y; acc.z += v.z; acc.w += v.w;
    }
    float dd = g_dis[d];
    acc.x *= dd; acc.y *= dd; acc.z *= dd; acc.w *= dd;
    red_add_v4(&g_pool[batch[d] * 128 + lane * 4], acc);
}

// out[g] = (pool[g]/max(cnt,1)) @ W2 + b2
__global__ void k_out(const float* __restrict__ W2, const float* __restrict__ b2,
                      float* __restrict__ out) {
    __shared__ float sp[128];
    int g = blockIdx.x, c = threadIdx.x;
    float inv = 1.0f / fmaxf(g_cnt[g], 1.0f);
    sp[c] = g_pool[g * 128 + c] * inv;
    __syncthreads();
    float acc = b2[c];
    #pragma unroll 8
    for (int k = 0; k < 128; k++)
        acc += sp[k] * W2[k * 128 + c];
    out[g * 128 + c] = acc;
}

// ---------------- launcher ---------------------------------------------------
extern "C" void kernel_launch(void* const* d_in, const int* in_sizes, int n_in,
                              void* d_out, int out_size) {
    const int*   x     = (const int*)d_in[0];
    const int*   ei    = (const int*)d_in[1];
    const int*   batch = (const int*)d_in[2];
    const float* emb   = (const float*)d_in[3];
    const float* W1    = (const float*)d_in[4];
    const float* b1    = (const float*)d_in[5];
    const float* W2    = (const float*)d_in[6];
    const float* b2    = (const float*)d_in[7];
    float* out = (float*)d_out;

    cudaFuncSetAttribute(k_fuse, cudaFuncAttributeMaxDynamicSharedMemorySize,
                         (16384 + 4096) * sizeof(float));

    k_zero   <<<(N_NODES + 255) / 256, 256>>>();
    k_count  <<<(N_EDGES + N_NODES + 255) / 256, 256>>>(ei, batch);
    k_scan1  <<<SCAN_BLOCKS, 256>>>();
    k_fuse   <<<SCAN_BLOCKS + EMBW_BLOCKS, 256, (16384 + 4096) * sizeof(float)>>>(emb, W1);
    k_scatter<<<(N_EDGES + 255) / 256, 256>>>(ei);
    k_agg0   <<<(N_NODES * 32 + 255) / 256, 256>>>(x, b1);
    k_agg1   <<<(N_NODES * 32 + 255) / 256, 256>>>(batch);
    k_out    <<<N_GRAPHS, 128>>>(W2, b2, out);
}

// round 16
// speedup vs baseline: 3.1690x; 1.0848x over previous
#include <cuda_runtime.h>
#include <cuda_fp16.h>
#include <cuda_bf16.h>

#define N_NODES  100000
#define N_EDGES  600000
#define N_GRAPHS 512
#define VOCABN   4096
#define EMBD     128
#define HIDD     128
#define SCAN_BLOCKS ((N_NODES + 255) / 256)   // 391
#define GEMM_BLOCKS (VOCABN / 16)             // 256 (16 rows per block)
#define COUNT_BLOCKS ((N_EDGES + N_NODES + 255) / 256)  // 2735
#define POOLZ_BLOCKS 64

// ---------------- scratch (device globals) ----------------------------------
__device__ float g_dis[N_NODES];
__device__ uint2 g_embWh[(size_t)VOCABN * 32];   // emb @ W1, fp16 (1 MB)
__device__ uint2 g_rh[(size_t)N_NODES * 32];     // relu(a0+b1)*dis, fp16 (25 MB)
__device__ float g_pool[N_GRAPHS * HIDD];
__device__ float g_cnt[N_GRAPHS];
__device__ int   g_rp[N_NODES + 1];              // CSR row pointer (by dst)
__device__ int   g_cur[N_NODES];                 // counts, then scatter cursor
__device__ int   g_bsum[512];                    // scan block sums
__device__ int   g_csp[N_EDGES];                 // packed (x[src]<<17 | src) by dst

__device__ __forceinline__ void red_add_v4(float* addr, float4 v) {
    asm volatile("red.global.add.v4.f32 [%0], {%1, %2, %3, %4};"
                 :: "l"(addr), "f"(v.x), "f"(v.y), "f"(v.z), "f"(v.w)
                 : "memory");
}

__device__ __forceinline__ uint2 pack_h4(float4 v) {
    __half2 a = __floats2half2_rn(v.x, v.y);
    __half2 b = __floats2half2_rn(v.z, v.w);
    uint2 r;
    r.x = *reinterpret_cast<unsigned*>(&a);
    r.y = *reinterpret_cast<unsigned*>(&b);
    return r;
}
__device__ __forceinline__ float4 unpack_h4(uint2 r) {
    float2 a = __half22float2(*reinterpret_cast<__half2*>(&r.x));
    float2 b = __half22float2(*reinterpret_cast<__half2*>(&r.y));
    return make_float4(a.x, a.y, b.x, b.y);
}

__device__ __forceinline__ int warp_incl_scan(int v, int lane) {
    #pragma unroll
    for (int o = 1; o < 32; o <<= 1) {
        int n = __shfl_up_sync(0xffffffffu, v, o);
        if (lane >= o) v += n;
    }
    return v;
}

// ---------------- kernels ---------------------------------------------------

// zero cur + cnt
__global__ void k_zero() {
    int i = blockIdx.x * blockDim.x + threadIdx.x;
    if (i < N_NODES) g_cur[i] = 0;
    if (i < N_GRAPHS) g_cnt[i] = 0.0f;
}

// Heterogeneous launch:
//   blocks [0, GEMM_BLOCKS):  embW = emb @ W1 (16 rows/block, fp16 out)
//   blocks [GEMM_BLOCKS, +COUNT_BLOCKS): degree histogram + batch histogram
__global__ void k_cg(const int* __restrict__ ei, const int* __restrict__ batch,
                     const float* __restrict__ emb, const float* __restrict__ W) {
    extern __shared__ float sm[];
    int tid = threadIdx.x;

    if (blockIdx.x >= GEMM_BLOCKS) {
        int i = (blockIdx.x - GEMM_BLOCKS) * 256 + tid;
        if (i < N_EDGES) {
            atomicAdd(&g_cur[ei[N_EDGES + i]], 1);
        } else {
            int j = i - N_EDGES;
            if (j < N_NODES) atomicAdd(&g_cnt[batch[j]], 1.0f);
        }
        return;
    }

    // ---- GEMM: 16 rows of emb @ W1 ----
    float* sW = sm;            // 128*128 fp32 = 64 KB
    float* sA = sm + 16384;    // 16*128 fp32  = 8 KB

    const float4* W4 = reinterpret_cast<const float4*>(W);
    for (int i = tid; i < 4096; i += 256)
        reinterpret_cast<float4*>(sW)[i] = W4[i];

    int row0 = blockIdx.x * 16;
    const float4* A4 = reinterpret_cast<const float4*>(emb + (size_t)row0 * 128);
    for (int i = tid; i < 512; i += 256)
        reinterpret_cast<float4*>(sA)[i] = A4[i];
    __syncthreads();

    int warp = tid >> 5, lane = tid & 31;
    int r0 = warp * 2;
    float4 acc0 = make_float4(0.f, 0.f, 0.f, 0.f);
    float4 acc1 = make_float4(0.f, 0.f, 0.f, 0.f);

    #pragma unroll 8
    for (int k = 0; k < 128; k++) {
        float4 w = reinterpret_cast<float4*>(sW + k * 128)[lane];
        float a0 = sA[r0 * 128 + k];
        float a1 = sA[(r0 + 1) * 128 + k];
        acc0.x += a0 * w.x; acc0.y += a0 * w.y;
        acc0.z += a0 * w.z; acc0.w += a0 * w.w;
        acc1.x += a1 * w.x; acc1.y += a1 * w.y;
        acc1.z += a1 * w.z; acc1.w += a1 * w.w;
    }
    g_embWh[(size_t)(row0 + r0)     * 32 + lane] = pack_h4(acc0);
    g_embWh[(size_t)(row0 + r0 + 1) * 32 + lane] = pack_h4(acc1);
}

// block-local exclusive scan (shuffle) -> g_rp partial, totals -> g_bsum,
// dis = rsqrt(1 + in_count).
__global__ void k_scan1() {
    __shared__ int ws[8];
    int tid = threadIdx.x, lane = tid & 31, w = tid >> 5;
    int i = blockIdx.x * 256 + tid;
    int c = (i < N_NODES) ? g_cur[i] : 0;
    if (i < N_NODES) g_dis[i] = rsqrtf(1.0f + (float)c);
    int s = warp_incl_scan(c, lane);
    if (lane == 31) ws[w] = s;
    __syncthreads();
    if (w == 0) {
        int v = (lane < 8) ? ws[lane] : 0;
        v = warp_incl_scan(v, lane);
        if (lane < 8) ws[lane] = v;
    }
    __syncthreads();
    int excl = s - c + (w > 0 ? ws[w - 1] : 0);
    if (i < N_NODES) g_rp[i] = excl;
    if (tid == 255) g_bsum[blockIdx.x] = ws[7];
}

// blocks [0, SCAN_BLOCKS): finalize CSR row pointers (own block-sum prefix)
// blocks [SCAN_BLOCKS, +POOLZ_BLOCKS): zero pool
__global__ void k_fin() {
    int tid = threadIdx.x;
    if (blockIdx.x >= SCAN_BLOCKS) {
        int i = (blockIdx.x - SCAN_BLOCKS) * 256 + tid;  // < 16384
        reinterpret_cast<float4*>(g_pool)[i] = make_float4(0.f, 0.f, 0.f, 0.f);
        return;
    }
    __shared__ int wred[8];
    __shared__ int s_off;
    int bid = blockIdx.x, lane = tid & 31, w = tid >> 5;
    int acc = 0;
    for (int j = tid; j < bid; j += 256) acc += g_bsum[j];
    #pragma unroll
    for (int o = 16; o > 0; o >>= 1)
        acc += __shfl_down_sync(0xffffffffu, acc, o);
    if (lane == 0) wred[w] = acc;
    __syncthreads();
    if (tid == 0) {
        int t = 0;
        #pragma unroll
        for (int k = 0; k < 8; k++) t += wred[k];
        s_off = t;
    }
    __syncthreads();
    int i = bid * 256 + tid;
    if (i < N_NODES) {
        int v = g_rp[i] + s_off;
        g_rp[i] = v;
        g_cur[i] = v;
    }
    if (bid == 0 && tid == 0) g_rp[N_NODES] = N_EDGES;
}

// bucket edges by dst, payload packed (x[src] << 17) | src
__global__ void k_scatter(const int* __restrict__ ei, const int* __restrict__ x) {
    int e = blockIdx.x * blockDim.x + threadIdx.x;
    if (e >= N_EDGES) return;
    int s = ei[e];
    int d = ei[N_EDGES + e];
    int xv = x[s];
    int pos = atomicAdd(&g_cur[d], 1);
    g_csp[pos] = (xv << 17) | s;
}

// layer-1 aggregation (gather form), warp per dst node, fused bias+relu+dis:
// r[d] = relu( dis[d]*(dis[d]*embW[x[d]] + sum_in dis[s]*embW[x[s]]) + b1 ) * dis[d]
__global__ void k_agg0(const int* __restrict__ x, const float* __restrict__ b1) {
    int t = blockIdx.x * blockDim.x + threadIdx.x;
    int d = t >> 5, lane = t & 31;
    if (d >= N_NODES) return;

    float dd = g_dis[d];
    float4 e = unpack_h4(g_embWh[(size_t)x[d] * 32 + lane]);
    float4 acc;
    acc.x = dd * e.x; acc.y = dd * e.y; acc.z = dd * e.z; acc.w = dd * e.w;

    int j = g_rp[d], jend = g_rp[d + 1];
    for (; j + 1 < jend; j += 2) {
        int p0 = g_csp[j], p1 = g_csp[j + 1];
        float d0 = g_dis[p0 & 0x1FFFF], d1 = g_dis[p1 & 0x1FFFF];
        float4 v0 = unpack_h4(g_embWh[(size_t)(p0 >> 17) * 32 + lane]);
        float4 v1 = unpack_h4(g_embWh[(size_t)(p1 >> 17) * 32 + lane]);
        acc.x += d0 * v0.x + d1 * v1.x;
        acc.y += d0 * v0.y + d1 * v1.y;
        acc.z += d0 * v0.z + d1 * v1.z;
        acc.w += d0 * v0.w + d1 * v1.w;
    }
    if (j < jend) {
        int p = g_csp[j];
        float ds = g_dis[p & 0x1FFFF];
        float4 v = unpack_h4(g_embWh[(size_t)(p >> 17) * 32 + lane]);
        acc.x += ds * v.x; acc.y += ds * v.y;
        acc.z += ds * v.z; acc.w += ds * v.w;
    }

    float4 bb = reinterpret_cast<const float4*>(b1)[lane];
    float4 r;
    r.x = fmaxf(dd * acc.x + bb.x, 0.f) * dd;
    r.y = fmaxf(dd * acc.y + bb.y, 0.f) * dd;
    r.z = fmaxf(dd * acc.z + bb.z, 0.f) * dd;
    r.w = fmaxf(dd * acc.w + bb.w, 0.f) * dd;
    g_rh[(size_t)d * 32 + lane] = pack_h4(r);
}

// layer-2 aggregation + pooling (gather form), warp per dst node:
// pool[batch[d]] += dis[d] * ( r[d] + sum_in r[s] )
__global__ void k_agg1(const int* __restrict__ batch) {
    int t = blockIdx.x * blockDim.x + threadIdx.x;
    int d = t >> 5, lane = t & 31;
    if (d >= N_NODES) return;

    float4 acc = unpack_h4(g_rh[(size_t)d * 32 + lane]);

    int j = g_rp[d], jend = g_rp[d + 1];
    for (; j + 1 < jend; j += 2) {
        int s0 = g_csp[j] & 0x1FFFF, s1 = g_csp[j + 1] & 0x1FFFF;
        float4 v0 = unpack_h4(g_rh[(size_t)s0 * 32 + lane]);
        float4 v1 = unpack_h4(g_rh[(size_t)s1 * 32 + lane]);
        acc.x += v0.x + v1.x; acc.y += v0.y + v1.y;
        acc.z += v0.z + v1.z; acc.w += v0.w + v1.w;
    }
    if (j < jend) {
        float4 v = unpack_h4(g_rh[(size_t)(g_csp[j] & 0x1FFFF) * 32 + lane]);
        acc.x += v.x; acc.y += v.y; acc.z += v.z; acc.w += v.w;
    }
    float dd = g_dis[d];
    acc.x *= dd; acc.y *= dd; acc.z *= dd; acc.w *= dd;
    red_add_v4(&g_pool[batch[d] * 128 + lane * 4], acc);
}

// out[g] = (pool[g]/max(cnt,1)) @ W2 + b2
__global__ void k_out(const float* __restrict__ W2, const float* __restrict__ b2,
                      float* __restrict__ out) {
    __shared__ float sp[128];
    int g = blockIdx.x, c = threadIdx.x;
    float inv = 1.0f / fmaxf(g_cnt[g], 1.0f);
    sp[c] = g_pool[g * 128 + c] * inv;
    __syncthreads();
    float acc = b2[c];
    #pragma unroll 8
    for (int k = 0; k < 128; k++)
        acc += sp[k] * W2[k * 128 + c];
    out[g * 128 + c] = acc;
}

// ---------------- launcher ---------------------------------------------------
extern "C" void kernel_launch(void* const* d_in, const int* in_sizes, int n_in,
                              void* d_out, int out_size) {
    const int*   x     = (const int*)d_in[0];
    const int*   ei    = (const int*)d_in[1];
    const int*   batch = (const int*)d_in[2];
    const float* emb   = (const float*)d_in[3];
    const float* W1    = (const float*)d_in[4];
    const float* b1    = (const float*)d_in[5];
    const float* W2    = (const float*)d_in[6];
    const float* b2    = (const float*)d_in[7];
    float* out = (float*)d_out;

    const int SMEM_CG = (16384 + 2048) * sizeof(float);   // 72 KB
    cudaFuncSetAttribute(k_cg, cudaFuncAttributeMaxDynamicSharedMemorySize, SMEM_CG);

    k_zero   <<<SCAN_BLOCKS, 256>>>();
    k_cg     <<<GEMM_BLOCKS + COUNT_BLOCKS, 256, SMEM_CG>>>(ei, batch, emb, W1);
    k_scan1  <<<SCAN_BLOCKS, 256>>>();
    k_fin    <<<SCAN_BLOCKS + POOLZ_BLOCKS, 256>>>();
    k_scatter<<<(N_EDGES + 255) / 256, 256>>>(ei, x);
    k_agg0   <<<(N_NODES * 32 + 255) / 256, 256>>>(x, b1);
    k_agg1   <<<(N_NODES * 32 + 255) / 256, 256>>>(batch);
    k_out    <<<N_GRAPHS, 128>>>(W2, b2, out);
}